// round 3
// baseline (speedup 1.0000x reference)
#include <cuda_runtime.h>
#include <cuda_bf16.h>

// SynergyPre: per-edge  logits = drug[i0] * drug[i1] * drug[i2]  (elementwise, D=128)
//             h1 = relu(logits @ W1^T + b1)   (32)
//             h2 = relu(h1 @ W2^T + b2)       (32)
//             h3 = relu(h2 @ W3^T + b3)       (32)
//             x  = sigmoid(h3 @ W4^T + b4)    (1)
// Output: [ x[0..E), label[0..E) ] as float32.
// cell_hidden_out / proj_W / proj_b are dead code in the reference.
// Edges arrive as int32 (harness converts int64 -> int32).

#define D_DIM 128
#define H_DIM 32
#define TPB   256

__global__ __launch_bounds__(TPB)
void synergy_kernel(const float* __restrict__ drug,        // [N_DRUGS, 128]
                    const int* __restrict__ edges,         // [E, 4] int32
                    const float* __restrict__ W1, const float* __restrict__ b1,
                    const float* __restrict__ W2, const float* __restrict__ b2,
                    const float* __restrict__ W3, const float* __restrict__ b3,
                    const float* __restrict__ W4, const float* __restrict__ b4,
                    float* __restrict__ out, int E, long long out_size)
{
    __shared__ float sW1[H_DIM * D_DIM];   // 16 KB, row-major [j][d]
    __shared__ float sW2[H_DIM * H_DIM];   // 4 KB
    __shared__ float sW3[H_DIM * H_DIM];   // 4 KB
    __shared__ float sW4[H_DIM];
    __shared__ float sb1[H_DIM], sb2[H_DIM], sb3[H_DIM];
    __shared__ float sb4;

    const int tid = threadIdx.x;
    for (int i = tid; i < H_DIM * D_DIM; i += TPB) sW1[i] = W1[i];
    for (int i = tid; i < H_DIM * H_DIM; i += TPB) { sW2[i] = W2[i]; sW3[i] = W3[i]; }
    if (tid < H_DIM) { sW4[tid] = W4[tid]; sb1[tid] = b1[tid]; sb2[tid] = b2[tid]; sb3[tid] = b3[tid]; }
    if (tid == 0) sb4 = b4[0];
    __syncthreads();

    const int e = blockIdx.x * TPB + tid;
    if (e >= E) return;

    // One 16B load: [i0, i1, i2, label]
    const int4 ed = reinterpret_cast<const int4*>(edges)[e];

    const float4* __restrict__ r0 = reinterpret_cast<const float4*>(drug + (long long)ed.x * D_DIM);
    const float4* __restrict__ r1 = reinterpret_cast<const float4*>(drug + (long long)ed.y * D_DIM);
    const float4* __restrict__ r2 = reinterpret_cast<const float4*>(drug + (long long)ed.z * D_DIM);

    // ---- Layer 1: h[j] = b1[j] + sum_d W1[j][d] * (r0[d]*r1[d]*r2[d]) ----
    float h[H_DIM];
    #pragma unroll
    for (int j = 0; j < H_DIM; j++) h[j] = sb1[j];

    const float4* sW1v = reinterpret_cast<const float4*>(sW1);

    #pragma unroll 2
    for (int c = 0; c < D_DIM / 4; c++) {
        const float4 a = r0[c];
        const float4 b = r1[c];
        const float4 g = r2[c];
        const float l0 = a.x * b.x * g.x;
        const float l1 = a.y * b.y * g.y;
        const float l2 = a.z * b.z * g.z;
        const float l3 = a.w * b.w * g.w;
        #pragma unroll
        for (int j = 0; j < H_DIM; j++) {
            const float4 w = sW1v[j * (D_DIM / 4) + c];   // uniform address -> LDS broadcast
            h[j] = fmaf(w.x, l0, fmaf(w.y, l1, fmaf(w.z, l2, fmaf(w.w, l3, h[j]))));
        }
    }
    #pragma unroll
    for (int j = 0; j < H_DIM; j++) h[j] = fmaxf(h[j], 0.0f);

    // ---- Layer 2 ----
    float g2[H_DIM];
    const float4* sW2v = reinterpret_cast<const float4*>(sW2);
    #pragma unroll
    for (int j = 0; j < H_DIM; j++) {
        float s = sb2[j];
        #pragma unroll
        for (int k = 0; k < H_DIM / 4; k++) {
            const float4 w = sW2v[j * (H_DIM / 4) + k];
            s = fmaf(w.x, h[4*k+0], fmaf(w.y, h[4*k+1], fmaf(w.z, h[4*k+2], fmaf(w.w, h[4*k+3], s))));
        }
        g2[j] = fmaxf(s, 0.0f);
    }

    // ---- Layer 3 (write back into h) ----
    const float4* sW3v = reinterpret_cast<const float4*>(sW3);
    #pragma unroll
    for (int j = 0; j < H_DIM; j++) {
        float s = sb3[j];
        #pragma unroll
        for (int k = 0; k < H_DIM / 4; k++) {
            const float4 w = sW3v[j * (H_DIM / 4) + k];
            s = fmaf(w.x, g2[4*k+0], fmaf(w.y, g2[4*k+1], fmaf(w.z, g2[4*k+2], fmaf(w.w, g2[4*k+3], s))));
        }
        h[j] = fmaxf(s, 0.0f);
    }

    // ---- Layer 4 + sigmoid ----
    float z = sb4;
    const float4* sW4v = reinterpret_cast<const float4*>(sW4);
    #pragma unroll
    for (int k = 0; k < H_DIM / 4; k++) {
        const float4 w = sW4v[k];
        z = fmaf(w.x, h[4*k+0], fmaf(w.y, h[4*k+1], fmaf(w.z, h[4*k+2], fmaf(w.w, h[4*k+3], z))));
    }
    const float x = 1.0f / (1.0f + expf(-z));

    if ((long long)e < out_size)       out[e]     = x;
    if ((long long)(E + e) < out_size) out[E + e] = (float)ed.w;
}

extern "C" void kernel_launch(void* const* d_in, const int* in_sizes, int n_in,
                              void* d_out, int out_size)
{
    // metadata order:
    // 0 drug_hidden_out [4096,128] f32
    // 1 cell_hidden_out (unused)
    // 2 all_edges [E,4] int32 (converted from int64)
    // 3 proj_W (unused), 4 proj_b (unused)
    // 5 W1, 6 b1, 7 W2, 8 b2, 9 W3, 10 b3, 11 W4, 12 b4
    const float* drug  = (const float*)d_in[0];
    const int*   edges = (const int*)d_in[2];
    const float* W1 = (const float*)d_in[5];
    const float* b1 = (const float*)d_in[6];
    const float* W2 = (const float*)d_in[7];
    const float* b2 = (const float*)d_in[8];
    const float* W3 = (const float*)d_in[9];
    const float* b3 = (const float*)d_in[10];
    const float* W4 = (const float*)d_in[11];
    const float* b4 = (const float*)d_in[12];

    const int E = in_sizes[2] / 4;
    float* out = (float*)d_out;

    const int grid = (E + TPB - 1) / TPB;
    synergy_kernel<<<grid, TPB>>>(drug, edges, W1, b1, W2, b2, W3, b3, W4, b4,
                                  out, E, (long long)out_size);
}

// round 5
// speedup vs baseline: 1.1265x; 1.1265x over previous
#include <cuda_runtime.h>
#include <cuda_bf16.h>

// SynergyPre on GB300 — R4: EPT=2 + packed f32x2 FMA, weights transposed in smem.
// per-edge: logits = drug[i0]*drug[i1]*drug[i2] (D=128)
//           h1..h3 = relu(MLP 128->32->32->32), x = sigmoid(->1)
// out = [x(E), label(E)] fp32. cell/proj inputs are dead code. Edges arrive int32.

#define D_DIM 128
#define H_DIM 32
#define TPB   128
#define EPT   2
#define TILE  (TPB * EPT)   // 256 edges per block

typedef unsigned long long u64;

__device__ __forceinline__ u64 fma2(u64 a, u64 b, u64 c) {
    u64 d; asm("fma.rn.f32x2 %0, %1, %2, %3;" : "=l"(d) : "l"(a), "l"(b), "l"(c)); return d;
}
__device__ __forceinline__ u64 splat2(float x) {
    u64 d; asm("mov.b64 %0, {%1, %1};" : "=l"(d) : "f"(x)); return d;
}
__device__ __forceinline__ u64 pack2(float lo, float hi) {
    u64 d; asm("mov.b64 %0, {%1, %2};" : "=l"(d) : "f"(lo), "f"(hi)); return d;
}
__device__ __forceinline__ float2 unpk2(u64 v) {
    float2 r; asm("mov.b64 {%0, %1}, %2;" : "=f"(r.x), "=f"(r.y) : "l"(v)); return r;
}

__global__ __launch_bounds__(TPB)
void synergy_kernel(const float* __restrict__ drug,   // [4096,128]
                    const int* __restrict__ edges,    // [E,4] int32
                    const float* __restrict__ W1, const float* __restrict__ b1,
                    const float* __restrict__ W2, const float* __restrict__ b2,
                    const float* __restrict__ W3, const float* __restrict__ b3,
                    const float* __restrict__ W4, const float* __restrict__ b4,
                    float* __restrict__ out, int E)
{
    // Transposed weights: j contiguous -> f32x2 pairs contiguous.
    __shared__ float sW1t[D_DIM * H_DIM];   // [d][j]  16 KB
    __shared__ float sW2t[H_DIM * H_DIM];   // [k][j]   4 KB
    __shared__ float sW3t[H_DIM * H_DIM];   // [k][j]   4 KB
    __shared__ float sW4[H_DIM];
    __shared__ float sb1[H_DIM], sb2[H_DIM], sb3[H_DIM];
    __shared__ float sb4;

    const int tid = threadIdx.x;
    for (int i = tid; i < D_DIM * H_DIM; i += TPB) {
        const int j = i / D_DIM, d = i % D_DIM;
        sW1t[d * H_DIM + j] = W1[i];
    }
    for (int i = tid; i < H_DIM * H_DIM; i += TPB) {
        const int j = i / H_DIM, k = i % H_DIM;
        sW2t[k * H_DIM + j] = W2[i];
        sW3t[k * H_DIM + j] = W3[i];
    }
    if (tid < H_DIM) { sW4[tid] = W4[tid]; sb1[tid] = b1[tid]; sb2[tid] = b2[tid]; sb3[tid] = b3[tid]; }
    if (tid == 0) sb4 = b4[0];
    __syncthreads();

    const int e0 = blockIdx.x * TILE + tid;
    const int e1 = e0 + TPB;
    const int ea = (e0 < E) ? e0 : (E - 1);     // clamp so loads stay in bounds
    const int eb = (e1 < E) ? e1 : (E - 1);

    const int4 edA = reinterpret_cast<const int4*>(edges)[ea];
    const int4 edB = reinterpret_cast<const int4*>(edges)[eb];

    const float4* __restrict__ rA0 = reinterpret_cast<const float4*>(drug + (long long)edA.x * D_DIM);
    const float4* __restrict__ rA1 = reinterpret_cast<const float4*>(drug + (long long)edA.y * D_DIM);
    const float4* __restrict__ rA2 = reinterpret_cast<const float4*>(drug + (long long)edA.z * D_DIM);
    const float4* __restrict__ rB0 = reinterpret_cast<const float4*>(drug + (long long)edB.x * D_DIM);
    const float4* __restrict__ rB1 = reinterpret_cast<const float4*>(drug + (long long)edB.y * D_DIM);
    const float4* __restrict__ rB2 = reinterpret_cast<const float4*>(drug + (long long)edB.z * D_DIM);

    // ---- Layer 1: 16 j-pairs per edge, accumulate in f32x2 ----
    u64 accA[H_DIM / 2], accB[H_DIM / 2];
    const u64* sb1p = reinterpret_cast<const u64*>(sb1);
    #pragma unroll
    for (int jp = 0; jp < H_DIM / 2; jp++) { accA[jp] = sb1p[jp]; accB[jp] = sb1p[jp]; }

    #pragma unroll 1
    for (int c = 0; c < D_DIM / 4; c++) {
        const float4 a0 = rA0[c], b0 = rA1[c], g0 = rA2[c];
        const float4 a1 = rB0[c], b1v = rB1[c], g1 = rB2[c];
        const float lA[4] = { a0.x*b0.x*g0.x, a0.y*b0.y*g0.y, a0.z*b0.z*g0.z, a0.w*b0.w*g0.w };
        const float lB[4] = { a1.x*b1v.x*g1.x, a1.y*b1v.y*g1.y, a1.z*b1v.z*g1.z, a1.w*b1v.w*g1.w };
        #pragma unroll
        for (int d = 0; d < 4; d++) {
            const u64 sA = splat2(lA[d]);
            const u64 sB = splat2(lB[d]);
            const ulonglong2* wrow = reinterpret_cast<const ulonglong2*>(sW1t + (c * 4 + d) * H_DIM);
            #pragma unroll
            for (int q = 0; q < H_DIM / 4; q++) {       // 8 x LDS.128, each = 2 j-pairs
                const ulonglong2 w = wrow[q];           // uniform address -> broadcast
                accA[2*q    ] = fma2(w.x, sA, accA[2*q    ]);
                accA[2*q + 1] = fma2(w.y, sA, accA[2*q + 1]);
                accB[2*q    ] = fma2(w.x, sB, accB[2*q    ]);
                accB[2*q + 1] = fma2(w.y, sB, accB[2*q + 1]);
            }
        }
    }

    float hA[H_DIM], hB[H_DIM];
    #pragma unroll
    for (int jp = 0; jp < H_DIM / 2; jp++) {
        const float2 fa = unpk2(accA[jp]); const float2 fb = unpk2(accB[jp]);
        hA[2*jp] = fmaxf(fa.x, 0.f); hA[2*jp+1] = fmaxf(fa.y, 0.f);
        hB[2*jp] = fmaxf(fb.x, 0.f); hB[2*jp+1] = fmaxf(fb.y, 0.f);
    }

    // ---- Layer 2 ----
    const u64* sb2p = reinterpret_cast<const u64*>(sb2);
    #pragma unroll
    for (int jp = 0; jp < H_DIM / 2; jp++) { accA[jp] = sb2p[jp]; accB[jp] = sb2p[jp]; }
    #pragma unroll 1
    for (int k = 0; k < H_DIM; k++) {
        const u64 sA = splat2(hA[k]);
        const u64 sB = splat2(hB[k]);
        const ulonglong2* wrow = reinterpret_cast<const ulonglong2*>(sW2t + k * H_DIM);
        #pragma unroll
        for (int q = 0; q < H_DIM / 4; q++) {
            const ulonglong2 w = wrow[q];
            accA[2*q    ] = fma2(w.x, sA, accA[2*q    ]);
            accA[2*q + 1] = fma2(w.y, sA, accA[2*q + 1]);
            accB[2*q    ] = fma2(w.x, sB, accB[2*q    ]);
            accB[2*q + 1] = fma2(w.y, sB, accB[2*q + 1]);
        }
    }
    #pragma unroll
    for (int jp = 0; jp < H_DIM / 2; jp++) {
        const float2 fa = unpk2(accA[jp]); const float2 fb = unpk2(accB[jp]);
        hA[2*jp] = fmaxf(fa.x, 0.f); hA[2*jp+1] = fmaxf(fa.y, 0.f);
        hB[2*jp] = fmaxf(fb.x, 0.f); hB[2*jp+1] = fmaxf(fb.y, 0.f);
    }

    // ---- Layer 3 ----
    const u64* sb3p = reinterpret_cast<const u64*>(sb3);
    #pragma unroll
    for (int jp = 0; jp < H_DIM / 2; jp++) { accA[jp] = sb3p[jp]; accB[jp] = sb3p[jp]; }
    #pragma unroll 1
    for (int k = 0; k < H_DIM; k++) {
        const u64 sA = splat2(hA[k]);
        const u64 sB = splat2(hB[k]);
        const ulonglong2* wrow = reinterpret_cast<const ulonglong2*>(sW3t + k * H_DIM);
        #pragma unroll
        for (int q = 0; q < H_DIM / 4; q++) {
            const ulonglong2 w = wrow[q];
            accA[2*q    ] = fma2(w.x, sA, accA[2*q    ]);
            accA[2*q + 1] = fma2(w.y, sA, accA[2*q + 1]);
            accB[2*q    ] = fma2(w.x, sB, accB[2*q    ]);
            accB[2*q + 1] = fma2(w.y, sB, accB[2*q + 1]);
        }
    }
    #pragma unroll
    for (int jp = 0; jp < H_DIM / 2; jp++) {
        const float2 fa = unpk2(accA[jp]); const float2 fb = unpk2(accB[jp]);
        hA[2*jp] = fmaxf(fa.x, 0.f); hA[2*jp+1] = fmaxf(fa.y, 0.f);
        hB[2*jp] = fmaxf(fb.x, 0.f); hB[2*jp+1] = fmaxf(fb.y, 0.f);
    }

    // ---- Layer 4 + sigmoid ----
    const u64* sW4p = reinterpret_cast<const u64*>(sW4);
    u64 zA = pack2(0.f, 0.f), zB = pack2(0.f, 0.f);
    #pragma unroll
    for (int jp = 0; jp < H_DIM / 2; jp++) {
        const u64 w = sW4p[jp];
        zA = fma2(w, pack2(hA[2*jp], hA[2*jp+1]), zA);
        zB = fma2(w, pack2(hB[2*jp], hB[2*jp+1]), zB);
    }
    const float2 za = unpk2(zA), zb = unpk2(zB);
    const float z0 = za.x + za.y + sb4;
    const float z1 = zb.x + zb.y + sb4;
    const float x0 = __fdividef(1.0f, 1.0f + __expf(-z0));
    const float x1 = __fdividef(1.0f, 1.0f + __expf(-z1));

    if (e0 < E) { out[e0] = x0; out[E + e0] = (float)edA.w; }
    if (e1 < E) { out[e1] = x1; out[E + e1] = (float)edB.w; }
}

extern "C" void kernel_launch(void* const* d_in, const int* in_sizes, int n_in,
                              void* d_out, int out_size)
{
    const float* drug  = (const float*)d_in[0];
    const int*   edges = (const int*)d_in[2];
    const float* W1 = (const float*)d_in[5];
    const float* b1 = (const float*)d_in[6];
    const float* W2 = (const float*)d_in[7];
    const float* b2 = (const float*)d_in[8];
    const float* W3 = (const float*)d_in[9];
    const float* b3 = (const float*)d_in[10];
    const float* W4 = (const float*)d_in[11];
    const float* b4 = (const float*)d_in[12];

    const int E = in_sizes[2] / 4;
    float* out = (float*)d_out;

    const int grid = (E + TILE - 1) / TILE;
    synergy_kernel<<<grid, TPB>>>(drug, edges, W1, b1, W2, b2, W3, b3, W4, b4, out, E);
}